// round 1
// baseline (speedup 1.0000x reference)
#include <cuda_runtime.h>
#include <math.h>

#define H 128
#define MAXB 8192

// scratch: segment-mean embeddings [B, H]
__device__ float g_sent[(size_t)MAXB * H];

// ---------------------------------------------------------------------------
// Kernel 1: gather + segment mean. One CTA per segment, 128 threads = one
// hidden dim each. segment_ids is sorted, so the segment's token range is
// found by binary search (no atomics anywhere).
// ---------------------------------------------------------------------------
__global__ __launch_bounds__(128) void seg_mean_kernel(
    const int* __restrict__ token_ids,
    const int* __restrict__ seg_ids,
    const float* __restrict__ embed,
    int T)
{
    const int seg = blockIdx.x;
    const int tid = threadIdx.x;  // 0..127 = hidden dim

    // lower_bound(seg) and lower_bound(seg+1); all threads redundantly (broadcast loads)
    int lo = 0, hi = T;
    while (lo < hi) {
        int mid = (lo + hi) >> 1;
        if (seg_ids[mid] < seg) lo = mid + 1; else hi = mid;
    }
    const int start = lo;
    hi = T;
    while (lo < hi) {
        int mid = (lo + hi) >> 1;
        if (seg_ids[mid] < seg + 1) lo = mid + 1; else hi = mid;
    }
    const int end = lo;

    __shared__ int s_tok[128];
    float a0 = 0.f, a1 = 0.f, a2 = 0.f, a3 = 0.f;

    for (int t0 = start; t0 < end; t0 += 128) {
        const int n = min(128, end - t0);
        __syncthreads();                       // protect s_tok reuse
        if (tid < n) s_tok[tid] = token_ids[t0 + tid];
        __syncthreads();
        int i = 0;
        for (; i + 4 <= n; i += 4) {           // 4 independent acc chains -> MLP>=4
            a0 += __ldg(embed + (size_t)s_tok[i + 0] * H + tid);
            a1 += __ldg(embed + (size_t)s_tok[i + 1] * H + tid);
            a2 += __ldg(embed + (size_t)s_tok[i + 2] * H + tid);
            a3 += __ldg(embed + (size_t)s_tok[i + 3] * H + tid);
        }
        for (; i < n; i++)
            a0 += __ldg(embed + (size_t)s_tok[i] * H + tid);
    }

    const int cnt = end - start;
    const float inv = 1.0f / (float)max(cnt, 1);
    g_sent[(size_t)seg * H + tid] = (a0 + a1 + a2 + a3) * inv;
}

// ---------------------------------------------------------------------------
// Kernel 2: MLP head + BCE(sum). One warp handles 4 rows (segments).
// Lane l owns hidden columns 4l..4l+3. W_hid rows are read as float4 and hit
// L1 across the many warps per SM. Stable log-sigmoid forms reproduce the
// reference's clip(log, -100) semantics exactly.
// ---------------------------------------------------------------------------
__global__ __launch_bounds__(256) void mlp_bce_kernel(
    const float* __restrict__ y_true,
    const float* __restrict__ W_hid,   // [H, H] row-major: W[k*H + j]
    const float* __restrict__ b_hid,   // [H]
    const float* __restrict__ W_out,   // [H]
    const float* __restrict__ b_out,   // [1]
    float* __restrict__ out,
    int B)
{
    const int warp = (blockIdx.x * blockDim.x + threadIdx.x) >> 5;
    const int lane = threadIdx.x & 31;
    const int row0 = warp * 4;
    if (row0 >= B) return;

    const float4* W4 = (const float4*)W_hid;   // W4[k*32 + l] = W[k][4l..4l+3]
    const float4 bh = ((const float4*)b_hid)[lane];

    float4 s[4];
    float4 acc[4];
#pragma unroll
    for (int r = 0; r < 4; r++) {
        int row = min(row0 + r, B - 1);
        s[r] = ((const float4*)g_sent)[(size_t)row * (H / 4) + lane];
        acc[r] = bh;
    }

#pragma unroll 4
    for (int kk = 0; kk < 32; kk++) {
        float4 sb[4];
#pragma unroll
        for (int r = 0; r < 4; r++) {
            sb[r].x = __shfl_sync(0xffffffffu, s[r].x, kk);
            sb[r].y = __shfl_sync(0xffffffffu, s[r].y, kk);
            sb[r].z = __shfl_sync(0xffffffffu, s[r].z, kk);
            sb[r].w = __shfl_sync(0xffffffffu, s[r].w, kk);
        }
#pragma unroll
        for (int c = 0; c < 4; c++) {
            const float4 wv = __ldg(&W4[(kk * 4 + c) * 32 + lane]);
#pragma unroll
            for (int r = 0; r < 4; r++) {
                const float sv = (c == 0) ? sb[r].x
                               : (c == 1) ? sb[r].y
                               : (c == 2) ? sb[r].z : sb[r].w;
                acc[r].x += sv * wv.x;
                acc[r].y += sv * wv.y;
                acc[r].z += sv * wv.z;
                acc[r].w += sv * wv.w;
            }
        }
    }

    const float4 wo = ((const float4*)W_out)[lane];
    const float bo = __ldg(b_out);

    float partial[4];
#pragma unroll
    for (int r = 0; r < 4; r++) {
        partial[r] = tanhf(acc[r].x) * wo.x
                   + tanhf(acc[r].y) * wo.y
                   + tanhf(acc[r].z) * wo.z
                   + tanhf(acc[r].w) * wo.w;
    }

#pragma unroll
    for (int off = 16; off > 0; off >>= 1) {
#pragma unroll
        for (int r = 0; r < 4; r++)
            partial[r] += __shfl_xor_sync(0xffffffffu, partial[r], off);
    }

    if (lane == 0) {
        float local = 0.f;
#pragma unroll
        for (int r = 0; r < 4; r++) {
            const int row = row0 + r;
            if (row < B) {
                const float z = partial[r] + bo;
                // log(sigmoid(z)) = -log1p(exp(-z)); log(1-sigmoid(z)) = -log1p(exp(z))
                float lp  = -log1pf(expf(-z));
                float l1m = -log1pf(expf(z));
                lp  = fmaxf(lp,  -100.0f);   // exp overflow -> -inf -> clamps to -100
                l1m = fmaxf(l1m, -100.0f);
                const float y = y_true[row];
                local += -(y * lp + (1.0f - y) * l1m);
            }
        }
        atomicAdd(out, local);
    }
}

// ---------------------------------------------------------------------------
extern "C" void kernel_launch(void* const* d_in, const int* in_sizes, int n_in,
                              void* d_out, int out_size)
{
    const int*   token_ids = (const int*)d_in[0];
    const int*   seg_ids   = (const int*)d_in[1];
    const float* y_true    = (const float*)d_in[2];
    const float* embed     = (const float*)d_in[3];
    const float* W_hid     = (const float*)d_in[4];
    const float* b_hid     = (const float*)d_in[5];
    const float* W_out     = (const float*)d_in[6];
    const float* b_out     = (const float*)d_in[7];

    const int T = in_sizes[0];
    const int B = in_sizes[2];
    float* out = (float*)d_out;

    cudaMemsetAsync(out, 0, sizeof(float));

    seg_mean_kernel<<<B, 128>>>(token_ids, seg_ids, embed, T);

    const int warps  = (B + 3) / 4;
    const int blocks = (warps * 32 + 255) / 256;
    mlp_bce_kernel<<<blocks, 256>>>(y_true, W_hid, b_hid, W_out, b_out, out, B);
}

// round 2
// speedup vs baseline: 1.0509x; 1.0509x over previous
#include <cuda_runtime.h>
#include <math.h>

#define H 128
#define MAXB 8192
#define ROWS 8   // rows (segments) per MLP block

// scratch: segment-mean embeddings [B, H]
__device__ float g_sent[(size_t)MAXB * H];

// ---------------------------------------------------------------------------
// Kernel 1: gather + segment mean. One CTA per segment, 128 threads = one
// hidden dim each. segment_ids is sorted, so the segment's token range is
// found by binary search (no atomics anywhere). Already at the L2 roofline.
// ---------------------------------------------------------------------------
__global__ __launch_bounds__(128) void seg_mean_kernel(
    const int* __restrict__ token_ids,
    const int* __restrict__ seg_ids,
    const float* __restrict__ embed,
    int T)
{
    const int seg = blockIdx.x;
    const int tid = threadIdx.x;  // 0..127 = hidden dim

    int lo = 0, hi = T;
    while (lo < hi) {
        int mid = (lo + hi) >> 1;
        if (seg_ids[mid] < seg) lo = mid + 1; else hi = mid;
    }
    const int start = lo;
    hi = T;
    while (lo < hi) {
        int mid = (lo + hi) >> 1;
        if (seg_ids[mid] < seg + 1) lo = mid + 1; else hi = mid;
    }
    const int end = lo;

    __shared__ int s_tok[128];
    float a0 = 0.f, a1 = 0.f, a2 = 0.f, a3 = 0.f;

    for (int t0 = start; t0 < end; t0 += 128) {
        const int n = min(128, end - t0);
        __syncthreads();
        if (tid < n) s_tok[tid] = token_ids[t0 + tid];
        __syncthreads();
        int i = 0;
        for (; i + 4 <= n; i += 4) {
            a0 += __ldg(embed + (size_t)s_tok[i + 0] * H + tid);
            a1 += __ldg(embed + (size_t)s_tok[i + 1] * H + tid);
            a2 += __ldg(embed + (size_t)s_tok[i + 2] * H + tid);
            a3 += __ldg(embed + (size_t)s_tok[i + 3] * H + tid);
        }
        for (; i < n; i++)
            a0 += __ldg(embed + (size_t)s_tok[i] * H + tid);
    }

    const int cnt = end - start;
    const float inv = 1.0f / (float)max(cnt, 1);
    g_sent[(size_t)seg * H + tid] = (a0 + a1 + a2 + a3) * inv;
}

// ---------------------------------------------------------------------------
// Kernel 2: MLP head + BCE(sum). One 128-thread block per 8 rows.
// Thread t computes hid[r][t] for all 8 rows. Sentence vectors are staged
// TRANSPOSED in shared (s_t[k][r]) so the mainloop per k is:
//   2x broadcast LDS.128 + 1 coalesced W load (L1-hot) + 8 FMA.
// No shuffles in the mainloop.
// ---------------------------------------------------------------------------
__global__ __launch_bounds__(128) void mlp_bce_kernel(
    const float* __restrict__ y_true,
    const float* __restrict__ W_hid,   // [H, H] row-major
    const float* __restrict__ b_hid,   // [H]
    const float* __restrict__ W_out,   // [H]
    const float* __restrict__ b_out,   // [1]
    float* __restrict__ out,
    int B)
{
    const int t    = threadIdx.x;          // hidden column
    const int row0 = blockIdx.x * ROWS;

    __shared__ float s_t[H][ROWS];          // transposed sentence vectors
    __shared__ float red[ROWS][4];          // per-warp reduction partials

#pragma unroll
    for (int r = 0; r < ROWS; r++) {
        const int row = min(row0 + r, B - 1);
        s_t[t][r] = g_sent[(size_t)row * H + t];
    }
    __syncthreads();

    float acc[ROWS];
    const float bh = b_hid[t];
#pragma unroll
    for (int r = 0; r < ROWS; r++) acc[r] = bh;

#pragma unroll 4
    for (int k = 0; k < H; k++) {
        const float  w  = __ldg(&W_hid[k * H + t]);
        const float4 sa = *(const float4*)&s_t[k][0];   // broadcast, conflict-free
        const float4 sb = *(const float4*)&s_t[k][4];
        acc[0] += sa.x * w;  acc[1] += sa.y * w;
        acc[2] += sa.z * w;  acc[3] += sa.w * w;
        acc[4] += sb.x * w;  acc[5] += sb.y * w;
        acc[6] += sb.z * w;  acc[7] += sb.w * w;
    }

    const float wo = W_out[t];
    float val[ROWS];
#pragma unroll
    for (int r = 0; r < ROWS; r++)
        val[r] = tanhf(acc[r]) * wo;

    // reduce each val[r] over the 128 threads
    const int lane = t & 31;
    const int wrp  = t >> 5;
#pragma unroll
    for (int off = 16; off > 0; off >>= 1)
#pragma unroll
        for (int r = 0; r < ROWS; r++)
            val[r] += __shfl_xor_sync(0xffffffffu, val[r], off);
    if (lane == 0)
#pragma unroll
        for (int r = 0; r < ROWS; r++) red[r][wrp] = val[r];
    __syncthreads();

    if (t < ROWS) {
        const int row = row0 + t;
        float loss = 0.f;
        if (row < B) {
            const float z = red[t][0] + red[t][1] + red[t][2] + red[t][3]
                          + __ldg(b_out);
            // log(sigmoid(z)) = -log1p(exp(-z)); log(1-sigmoid) = -log1p(exp(z))
            float lp  = fmaxf(-log1pf(expf(-z)), -100.0f);
            float l1m = fmaxf(-log1pf(expf(z)),  -100.0f);
            const float y = y_true[row];
            loss = -(y * lp + (1.0f - y) * l1m);
        }
#pragma unroll
        for (int off = 4; off > 0; off >>= 1)
            loss += __shfl_xor_sync(0x000000ffu, loss, off);
        if (t == 0) atomicAdd(out, loss);
    }
}

// ---------------------------------------------------------------------------
extern "C" void kernel_launch(void* const* d_in, const int* in_sizes, int n_in,
                              void* d_out, int out_size)
{
    const int*   token_ids = (const int*)d_in[0];
    const int*   seg_ids   = (const int*)d_in[1];
    const float* y_true    = (const float*)d_in[2];
    const float* embed     = (const float*)d_in[3];
    const float* W_hid     = (const float*)d_in[4];
    const float* b_hid     = (const float*)d_in[5];
    const float* W_out     = (const float*)d_in[6];
    const float* b_out     = (const float*)d_in[7];

    const int T = in_sizes[0];
    const int B = in_sizes[2];
    float* out = (float*)d_out;

    cudaMemsetAsync(out, 0, sizeof(float));

    seg_mean_kernel<<<B, 128>>>(token_ids, seg_ids, embed, T);

    const int blocks = (B + ROWS - 1) / ROWS;
    mlp_bce_kernel<<<blocks, 128>>>(y_true, W_hid, b_hid, W_out, b_out, out, B);
}

// round 3
// speedup vs baseline: 1.2485x; 1.1881x over previous
#include <cuda_runtime.h>
#include <math.h>

#define H 128
#define MAXB 8192

// segment start offsets (allocation-free scratch)
__device__ int g_starts[MAXB + 1];

// ---------------------------------------------------------------------------
// Kernel 0: build segment start offsets from sorted segment_ids.
// starts[s] = first index with seg_ids[i] >= s; starts[B] = T.
// Each boundary is written exactly once (handles empty segments).
// ---------------------------------------------------------------------------
__global__ __launch_bounds__(256) void seg_starts_kernel(
    const int* __restrict__ seg_ids, int T, int B)
{
    const int i = blockIdx.x * blockDim.x + threadIdx.x;
    if (i >= T) return;
    const int cur  = seg_ids[i];
    const int prev = (i == 0) ? -1 : seg_ids[i - 1];
    for (int s = prev + 1; s <= cur; s++) g_starts[s] = i;
    if (i == T - 1)
        for (int s = cur + 1; s <= B; s++) g_starts[s] = T;
}

// ---------------------------------------------------------------------------
// Kernel 1 (fused): gather + segment-mean + MLP head + BCE.
// One CTA per segment, 128 threads = one hidden dim each.
// The matvec issue-work hides under the L2-bound gather of co-resident CTAs.
// ---------------------------------------------------------------------------
__global__ __launch_bounds__(128) void fused_dan_kernel(
    const int*   __restrict__ token_ids,
    const float* __restrict__ embed,
    const float* __restrict__ y_true,
    const float* __restrict__ W_hid,   // [H, H] row-major
    const float* __restrict__ b_hid,   // [H]
    const float* __restrict__ W_out,   // [H]
    const float* __restrict__ b_out,   // [1]
    float*       __restrict__ out,
    int B)
{
    const int seg = blockIdx.x;
    const int tid = threadIdx.x;            // hidden dim

    const int start = g_starts[seg];
    const int end   = g_starts[seg + 1];

    __shared__ int   s_tok[128];
    __shared__ float s_vec[H];               // sentence mean vector
    __shared__ float s_red[4];               // cross-warp reduction

    // ---- gather + mean ----
    float a0 = 0.f, a1 = 0.f, a2 = 0.f, a3 = 0.f;
    for (int t0 = start; t0 < end; t0 += 128) {
        const int n = min(128, end - t0);
        __syncthreads();
        if (tid < n) s_tok[tid] = token_ids[t0 + tid];
        __syncthreads();
        int i = 0;
        for (; i + 4 <= n; i += 4) {
            a0 += __ldg(embed + (size_t)s_tok[i + 0] * H + tid);
            a1 += __ldg(embed + (size_t)s_tok[i + 1] * H + tid);
            a2 += __ldg(embed + (size_t)s_tok[i + 2] * H + tid);
            a3 += __ldg(embed + (size_t)s_tok[i + 3] * H + tid);
        }
        for (; i < n; i++)
            a0 += __ldg(embed + (size_t)s_tok[i] * H + tid);
    }
    const int cnt = end - start;
    const float inv = 1.0f / (float)max(cnt, 1);
    s_vec[tid] = (a0 + a1 + a2 + a3) * inv;
    __syncthreads();

    // ---- hidden matvec: hid[tid] = tanh(b_hid[tid] + sum_k s[k]*W[k][tid]) ----
    float c0 = b_hid[tid], c1 = 0.f, c2 = 0.f, c3 = 0.f;  // 4 chains
#pragma unroll 8
    for (int k = 0; k < H; k += 4) {
        const float4 sv = *(const float4*)&s_vec[k];       // broadcast LDS.128
        c0 += sv.x * __ldg(&W_hid[(k + 0) * H + tid]);
        c1 += sv.y * __ldg(&W_hid[(k + 1) * H + tid]);
        c2 += sv.z * __ldg(&W_hid[(k + 2) * H + tid]);
        c3 += sv.w * __ldg(&W_hid[(k + 3) * H + tid]);
    }
    float val = tanhf((c0 + c1) + (c2 + c3)) * W_out[tid];

    // ---- reduce over 128 threads ----
#pragma unroll
    for (int off = 16; off > 0; off >>= 1)
        val += __shfl_xor_sync(0xffffffffu, val, off);
    if ((tid & 31) == 0) s_red[tid >> 5] = val;
    __syncthreads();

    if (tid == 0) {
        const float z = (s_red[0] + s_red[1]) + (s_red[2] + s_red[3]) + __ldg(b_out);
        // log(sigmoid(z)) = -log1p(exp(-z)); log(1-sigmoid(z)) = -log1p(exp(z))
        const float lp  = fmaxf(-log1pf(expf(-z)), -100.0f);
        const float l1m = fmaxf(-log1pf(expf(z)),  -100.0f);
        const float y   = y_true[seg];
        atomicAdd(out, -(y * lp + (1.0f - y) * l1m));
    }
}

// ---------------------------------------------------------------------------
extern "C" void kernel_launch(void* const* d_in, const int* in_sizes, int n_in,
                              void* d_out, int out_size)
{
    const int*   token_ids = (const int*)d_in[0];
    const int*   seg_ids   = (const int*)d_in[1];
    const float* y_true    = (const float*)d_in[2];
    const float* embed     = (const float*)d_in[3];
    const float* W_hid     = (const float*)d_in[4];
    const float* b_hid     = (const float*)d_in[5];
    const float* W_out     = (const float*)d_in[6];
    const float* b_out     = (const float*)d_in[7];

    const int T = in_sizes[0];
    const int B = in_sizes[2];
    float* out = (float*)d_out;

    cudaMemsetAsync(out, 0, sizeof(float));

    seg_starts_kernel<<<(T + 255) / 256, 256>>>(seg_ids, T, B);

    fused_dan_kernel<<<B, 128>>>(token_ids, embed, y_true,
                                 W_hid, b_hid, W_out, b_out, out, B);
}